// round 4
// baseline (speedup 1.0000x reference)
#include <cuda_runtime.h>

// HorizontalWidthTokenPyramid: x [32, 256, 32, 16, 16] f32
//   -> out [N*C*S, 31, 4] f32
// Per (n,c,s) 16x16 slice: for b in {16,8,4,2,1}: bin H into b bins
// (mean+max per column), then pool W 16->4 tokens (mean+max). Concat -> 31.
//
// Mapping (R2-proven): 4 threads/slice, thread q owns cols 4q..4q+3 (one
// token) -> one float4 (LDG.128) per row, zero shuffles. Pyramid folded
// progressively so only one accumulator per level is live. R4 change:
// launch_bounds(256,5) forces regs<=48 -> 5 blocks/SM (40 warps) instead
// of 4, plus streaming ld/st hints.

namespace {

constexpr int THREADS          = 256;
constexpr int SLICES_PER_BLOCK = 64;        // THREADS / 4
constexpr int OUT_PER_SLICE    = 31 * 4;    // 124
constexpr int SLICE_FLOATS     = 256;       // 16*16
constexpr int SMEM_FLOATS      = SLICES_PER_BLOCK * OUT_PER_SLICE;  // 7936

__device__ __forceinline__ float max4(float a, float b, float c, float d) {
    return fmaxf(fmaxf(a, b), fmaxf(c, d));
}
__device__ __forceinline__ float sum4(float a, float b, float c, float d) {
    return (a + b) + (c + d);
}
// token output for a bin: z_c = inv*sum_c + max_c ; out = 0.25*sum(z) + max(z)
__device__ __forceinline__ float token(const float s[4], const float m[4], float inv) {
    const float z0 = inv * s[0] + m[0];
    const float z1 = inv * s[1] + m[1];
    const float z2 = inv * s[2] + m[2];
    const float z3 = inv * s[3] + m[3];
    return 0.25f * sum4(z0, z1, z2, z3) + max4(z0, z1, z2, z3);
}

__global__ __launch_bounds__(THREADS, 5)
void hwtp_kernel(const float4* __restrict__ x4, float* __restrict__ out) {
    __shared__ float sm[SMEM_FLOATS];  // 31744 B

    const int tid = threadIdx.x;
    const int sl  = tid >> 2;   // local slice 0..63
    const int q   = tid & 3;    // width token 0..3

    const long slice = (long)blockIdx.x * SLICES_PER_BLOCK + sl;
    const float4* p = x4 + slice * (SLICE_FLOATS / 4) + q;

    float* o = &sm[sl * OUT_PER_SLICE + q];   // write o[bin*4]

    // running accumulators (sum,max per column) per pyramid level
    float s4v[4], m4v[4];   // level b=4  (4 rows)
    float s2v[4], m2v[4];   // level b=2  (8 rows)
    float s1v[4], m1v[4];   // level b=1  (16 rows)

    #pragma unroll
    for (int i = 0; i < 8; ++i) {           // row pair i = rows 2i, 2i+1
        const float4 v0 = __ldcs(&p[(2 * i) * 4]);
        const float4 v1 = __ldcs(&p[(2 * i + 1) * 4]);

        // level b=16 (bin size 1): mean+max over 1 row = 2*row
        o[(2 * i) * 4]     = 0.5f * sum4(v0.x, v0.y, v0.z, v0.w)
                           + 2.0f * max4(v0.x, v0.y, v0.z, v0.w);
        o[(2 * i + 1) * 4] = 0.5f * sum4(v1.x, v1.y, v1.z, v1.w)
                           + 2.0f * max4(v1.x, v1.y, v1.z, v1.w);

        // pair (level b=8 bin)
        float ps[4] = { v0.x + v1.x, v0.y + v1.y, v0.z + v1.z, v0.w + v1.w };
        float pm[4] = { fmaxf(v0.x, v1.x), fmaxf(v0.y, v1.y),
                        fmaxf(v0.z, v1.z), fmaxf(v0.w, v1.w) };
        o[(16 + i) * 4] = token(ps, pm, 0.5f);

        // fold pair into level b=4
        if ((i & 1) == 0) {
            #pragma unroll
            for (int c = 0; c < 4; ++c) { s4v[c] = ps[c]; m4v[c] = pm[c]; }
        } else {
            #pragma unroll
            for (int c = 0; c < 4; ++c) {
                s4v[c] += ps[c]; m4v[c] = fmaxf(m4v[c], pm[c]);
            }
            const int j = i >> 1;           // completed level-4 bin
            o[(24 + j) * 4] = token(s4v, m4v, 0.25f);

            // fold level-4 bin into level b=2
            if ((j & 1) == 0) {
                #pragma unroll
                for (int c = 0; c < 4; ++c) { s2v[c] = s4v[c]; m2v[c] = m4v[c]; }
            } else {
                #pragma unroll
                for (int c = 0; c < 4; ++c) {
                    s2v[c] += s4v[c]; m2v[c] = fmaxf(m2v[c], m4v[c]);
                }
                const int t = j >> 1;       // completed level-2 bin
                o[(28 + t) * 4] = token(s2v, m2v, 0.125f);

                // fold level-2 bin into level b=1
                if (t == 0) {
                    #pragma unroll
                    for (int c = 0; c < 4; ++c) { s1v[c] = s2v[c]; m1v[c] = m2v[c]; }
                } else {
                    #pragma unroll
                    for (int c = 0; c < 4; ++c) {
                        s1v[c] += s2v[c]; m1v[c] = fmaxf(m1v[c], m2v[c]);
                    }
                    o[30 * 4] = token(s1v, m1v, 0.0625f);
                }
            }
        }
    }

    __syncthreads();

    // Coalesced streaming flush: 7936 contiguous floats per block
    float* ob = out + (long)blockIdx.x * SMEM_FLOATS;
    constexpr int ITERS = SMEM_FLOATS / THREADS;  // 31
    #pragma unroll
    for (int i = 0; i < ITERS; ++i)
        __stcs(&ob[i * THREADS + tid], sm[i * THREADS + tid]);
}

}  // namespace

extern "C" void kernel_launch(void* const* d_in, const int* in_sizes, int n_in,
                              void* d_out, int out_size) {
    const float* x = (const float*)d_in[0];
    float* out = (float*)d_out;

    const long total_floats = (long)in_sizes[0];         // 67,108,864
    const long slices = total_floats / SLICE_FLOATS;     // 262,144
    const int blocks = (int)(slices / SLICES_PER_BLOCK); // 4096

    hwtp_kernel<<<blocks, THREADS>>>(reinterpret_cast<const float4*>(x), out);
}

// round 5
// speedup vs baseline: 1.0078x; 1.0078x over previous
#include <cuda_runtime.h>
#include <cstdint>

// HorizontalWidthTokenPyramid: x [32, 256, 32, 16, 16] f32
//   -> out [N*C*S, 31, 4] f32
// Per 16x16 slice: for b in {16,8,4,2,1}: bin H (mean+max per col), then
// pool W 16->4 tokens (mean+max). Concat -> 31 bins.
//
// R5: cp.async.cg stages each block's input (32 slices = 32KB) into smem,
// decoupling memory-level parallelism from the register file (R2-R4 showed
// regs<->MLP coupling caps DRAM at ~80%). Compute = R2's 4-threads/slice
// progressive pyramid fold, reading conflict-free padded smem (stride
// 1088B). Outputs stored directly to global (L2 write-back merges the
// 16B-per-slice-bin writes into full sectors) - no staging, no flush.

namespace {

constexpr int THREADS          = 128;
constexpr int SLICES_PER_BLOCK = 32;
constexpr int SLICE_FLOATS     = 256;            // 16*16
constexpr int SLICE_STRIDE_F   = 272;            // 1088 B padded (68 x 16B)
constexpr int OUT_PER_SLICE    = 31 * 4;         // 124
constexpr int CHUNKS           = SLICES_PER_BLOCK * 64;   // 16B chunks = 2048
constexpr int CHUNKS_PER_THR   = CHUNKS / THREADS;        // 16

__device__ __forceinline__ float max4(float a, float b, float c, float d) {
    return fmaxf(fmaxf(a, b), fmaxf(c, d));
}
__device__ __forceinline__ float sum4(float a, float b, float c, float d) {
    return (a + b) + (c + d);
}
// token output for a bin: z_c = inv*sum_c + max_c ; out = 0.25*sum(z) + max(z)
__device__ __forceinline__ float token(const float s[4], const float m[4], float inv) {
    const float z0 = inv * s[0] + m[0];
    const float z1 = inv * s[1] + m[1];
    const float z2 = inv * s[2] + m[2];
    const float z3 = inv * s[3] + m[3];
    return 0.25f * sum4(z0, z1, z2, z3) + max4(z0, z1, z2, z3);
}

__global__ __launch_bounds__(THREADS, 6)
void hwtp_kernel(const float4* __restrict__ x4, float* __restrict__ out) {
    __shared__ float smem_in[SLICES_PER_BLOCK * SLICE_STRIDE_F];  // 34816 B

    const int tid = threadIdx.x;

    // ---- Phase 1: stage 32 slices (32KB) into smem via cp.async.cg ----
    {
        const uint32_t smem_base =
            (uint32_t)__cvta_generic_to_shared(&smem_in[0]);
        const char* gbase =
            (const char*)(x4 + (long)blockIdx.x * (SLICES_PER_BLOCK * SLICE_FLOATS / 4));
        #pragma unroll
        for (int k = 0; k < CHUNKS_PER_THR; ++k) {
            const int g     = tid + k * THREADS;     // 16B chunk index
            const int slice = g >> 6;                // 64 chunks per slice
            const int c     = g & 63;
            const uint32_t dst = smem_base + slice * 1088 + c * 16;
            const char* src = gbase + (long)g * 16;
            asm volatile("cp.async.cg.shared.global [%0], [%1], 16;\n"
                         :: "r"(dst), "l"(src));
        }
        asm volatile("cp.async.commit_group;\n" ::: "memory");
        asm volatile("cp.async.wait_group 0;\n" ::: "memory");
    }
    __syncthreads();

    // ---- Phase 2: pyramid fold from smem, direct global stores ----
    const int sl = tid >> 2;    // local slice 0..31
    const int q  = tid & 3;     // width token 0..3 (cols 4q..4q+3)

    const float* base = &smem_in[sl * SLICE_STRIDE_F + q * 4];
    float* o = out + ((long)blockIdx.x * SLICES_PER_BLOCK + sl) * OUT_PER_SLICE + q;

    float s4v[4], m4v[4];   // level b=4  accumulators
    float s2v[4], m2v[4];   // level b=2
    float s1v[4], m1v[4];   // level b=1

    #pragma unroll
    for (int i = 0; i < 8; ++i) {           // row pair: rows 2i, 2i+1
        const float4 v0 = *reinterpret_cast<const float4*>(base + (2 * i) * 16);
        const float4 v1 = *reinterpret_cast<const float4*>(base + (2 * i + 1) * 16);

        // level b=16 (single-row bins): mean+max over 1 row = 2*row
        o[(2 * i) * 4]     = 0.5f * sum4(v0.x, v0.y, v0.z, v0.w)
                           + 2.0f * max4(v0.x, v0.y, v0.z, v0.w);
        o[(2 * i + 1) * 4] = 0.5f * sum4(v1.x, v1.y, v1.z, v1.w)
                           + 2.0f * max4(v1.x, v1.y, v1.z, v1.w);

        // pair = level b=8 bin
        float ps[4] = { v0.x + v1.x, v0.y + v1.y, v0.z + v1.z, v0.w + v1.w };
        float pm[4] = { fmaxf(v0.x, v1.x), fmaxf(v0.y, v1.y),
                        fmaxf(v0.z, v1.z), fmaxf(v0.w, v1.w) };
        o[(16 + i) * 4] = token(ps, pm, 0.5f);

        // fold into level b=4
        if ((i & 1) == 0) {
            #pragma unroll
            for (int c = 0; c < 4; ++c) { s4v[c] = ps[c]; m4v[c] = pm[c]; }
        } else {
            #pragma unroll
            for (int c = 0; c < 4; ++c) {
                s4v[c] += ps[c]; m4v[c] = fmaxf(m4v[c], pm[c]);
            }
            const int j = i >> 1;
            o[(24 + j) * 4] = token(s4v, m4v, 0.25f);

            // fold into level b=2
            if ((j & 1) == 0) {
                #pragma unroll
                for (int c = 0; c < 4; ++c) { s2v[c] = s4v[c]; m2v[c] = m4v[c]; }
            } else {
                #pragma unroll
                for (int c = 0; c < 4; ++c) {
                    s2v[c] += s4v[c]; m2v[c] = fmaxf(m2v[c], m4v[c]);
                }
                const int t = j >> 1;
                o[(28 + t) * 4] = token(s2v, m2v, 0.125f);

                // fold into level b=1
                if (t == 0) {
                    #pragma unroll
                    for (int c = 0; c < 4; ++c) { s1v[c] = s2v[c]; m1v[c] = m2v[c]; }
                } else {
                    #pragma unroll
                    for (int c = 0; c < 4; ++c) {
                        s1v[c] += s2v[c]; m1v[c] = fmaxf(m1v[c], m2v[c]);
                    }
                    o[30 * 4] = token(s1v, m1v, 0.0625f);
                }
            }
        }
    }
}

}  // namespace

extern "C" void kernel_launch(void* const* d_in, const int* in_sizes, int n_in,
                              void* d_out, int out_size) {
    const float* x = (const float*)d_in[0];
    float* out = (float*)d_out;

    const long total_floats = (long)in_sizes[0];          // 67,108,864
    const long slices = total_floats / SLICE_FLOATS;      // 262,144
    const int blocks = (int)(slices / SLICES_PER_BLOCK);  // 8192

    hwtp_kernel<<<blocks, THREADS>>>(reinterpret_cast<const float4*>(x), out);
}

// round 6
// speedup vs baseline: 1.0661x; 1.0579x over previous
#include <cuda_runtime.h>
#include <cstdint>

// HorizontalWidthTokenPyramid: x [32, 256, 32, 16, 16] f32
//   -> out [N*C*S, 31, 4] f32
// Per 16x16 slice: for b in {16,8,4,2,1}: bin H (mean+max per col), then
// pool W 16->4 tokens (mean+max). Concat -> 31 bins.
//
// R6: cp.async.cg stages input (MLP in async queue, not registers; 6
// blocks/SM = 192KB in flight). Fold keeps all 31 outputs in REGISTERS,
// then writes them back into the consumed input smem region, and flushes
// fully coalesced (R5 showed scattered 16B output stores double L2 traffic
// and cap DRAM).

namespace {

constexpr int THREADS          = 128;
constexpr int SLICES_PER_BLOCK = 32;
constexpr int SLICE_FLOATS     = 256;            // 16*16
constexpr int SLICE_STRIDE_F   = 272;            // 1088 B (68 x 16B, ≡4 mod 8)
constexpr int OUT_PER_SLICE    = 31 * 4;         // 124
constexpr int BLOCK_OUT_FLOATS = SLICES_PER_BLOCK * OUT_PER_SLICE;  // 3968
constexpr int CHUNKS_PER_THR   = SLICES_PER_BLOCK * 64 / THREADS;   // 16

__device__ __forceinline__ float max4(float a, float b, float c, float d) {
    return fmaxf(fmaxf(a, b), fmaxf(c, d));
}
__device__ __forceinline__ float sum4(float a, float b, float c, float d) {
    return (a + b) + (c + d);
}
// token for a bin: z_c = inv*sum_c + max_c ; out = 0.25*sum(z) + max(z)
__device__ __forceinline__ float token(const float s[4], const float m[4], float inv) {
    const float z0 = inv * s[0] + m[0];
    const float z1 = inv * s[1] + m[1];
    const float z2 = inv * s[2] + m[2];
    const float z3 = inv * s[3] + m[3];
    return 0.25f * sum4(z0, z1, z2, z3) + max4(z0, z1, z2, z3);
}

__global__ __launch_bounds__(THREADS, 6)
void hwtp_kernel(const float4* __restrict__ x4, float* __restrict__ out) {
    __shared__ float smem[SLICES_PER_BLOCK * SLICE_STRIDE_F];  // 34816 B

    const int tid = threadIdx.x;

    // ---- Phase 1: stage 32 slices (32KB) via cp.async.cg ----
    {
        const uint32_t sbase = (uint32_t)__cvta_generic_to_shared(&smem[0]);
        const char* gbase =
            (const char*)(x4 + (long)blockIdx.x * (SLICES_PER_BLOCK * SLICE_FLOATS / 4));
        #pragma unroll
        for (int k = 0; k < CHUNKS_PER_THR; ++k) {
            const int g     = tid + k * THREADS;   // 16B chunk index
            const int slice = g >> 6;
            const int c     = g & 63;
            const uint32_t dst = sbase + slice * 1088 + c * 16;
            asm volatile("cp.async.cg.shared.global [%0], [%1], 16;\n"
                         :: "r"(dst), "l"(gbase + (long)g * 16));
        }
        asm volatile("cp.async.commit_group;\n" ::: "memory");
        asm volatile("cp.async.wait_group 0;\n" ::: "memory");
    }
    __syncthreads();

    // ---- Phase 2: pyramid fold, outputs buffered in registers ----
    const int sl = tid >> 2;    // local slice 0..31 (slice's 4 thr in 1 warp)
    const int q  = tid & 3;     // width token 0..3 (cols 4q..4q+3)

    const float* base = &smem[sl * SLICE_STRIDE_F + q * 4];

    float rb[31];               // all indices static -> stays in registers
    float s4v[4], m4v[4];       // level b=4 accumulators
    float s2v[4], m2v[4];       // level b=2
    float s1v[4], m1v[4];       // level b=1

    #pragma unroll
    for (int i = 0; i < 8; ++i) {           // row pair: rows 2i, 2i+1
        const float4 v0 = *reinterpret_cast<const float4*>(base + (2 * i) * 16);
        const float4 v1 = *reinterpret_cast<const float4*>(base + (2 * i + 1) * 16);

        // level b=16 (bin of 1 row): z = 2*row
        rb[2 * i]     = 0.5f * sum4(v0.x, v0.y, v0.z, v0.w)
                      + 2.0f * max4(v0.x, v0.y, v0.z, v0.w);
        rb[2 * i + 1] = 0.5f * sum4(v1.x, v1.y, v1.z, v1.w)
                      + 2.0f * max4(v1.x, v1.y, v1.z, v1.w);

        // pair = level b=8 bin
        float ps[4] = { v0.x + v1.x, v0.y + v1.y, v0.z + v1.z, v0.w + v1.w };
        float pm[4] = { fmaxf(v0.x, v1.x), fmaxf(v0.y, v1.y),
                        fmaxf(v0.z, v1.z), fmaxf(v0.w, v1.w) };
        rb[16 + i] = token(ps, pm, 0.5f);

        // fold into level b=4
        if ((i & 1) == 0) {
            #pragma unroll
            for (int c = 0; c < 4; ++c) { s4v[c] = ps[c]; m4v[c] = pm[c]; }
        } else {
            #pragma unroll
            for (int c = 0; c < 4; ++c) {
                s4v[c] += ps[c]; m4v[c] = fmaxf(m4v[c], pm[c]);
            }
            const int j = i >> 1;
            rb[24 + j] = token(s4v, m4v, 0.25f);

            // fold into level b=2
            if ((j & 1) == 0) {
                #pragma unroll
                for (int c = 0; c < 4; ++c) { s2v[c] = s4v[c]; m2v[c] = m4v[c]; }
            } else {
                #pragma unroll
                for (int c = 0; c < 4; ++c) {
                    s2v[c] += s4v[c]; m2v[c] = fmaxf(m2v[c], m4v[c]);
                }
                const int t = j >> 1;
                rb[28 + t] = token(s2v, m2v, 0.125f);

                // fold into level b=1
                if (t == 0) {
                    #pragma unroll
                    for (int c = 0; c < 4; ++c) { s1v[c] = s2v[c]; m1v[c] = m2v[c]; }
                } else {
                    #pragma unroll
                    for (int c = 0; c < 4; ++c) {
                        s1v[c] += s2v[c]; m1v[c] = fmaxf(m1v[c], m2v[c]);
                    }
                    rb[30] = token(s1v, m1v, 0.0625f);
                }
            }
        }
    }

    // ---- Phase 3: write outputs into the consumed input region ----
    // Slice region [0,496B) of [0,1088B); its only readers (this slice's 4
    // threads, same warp) finished all LDS above in program order.
    {
        float* o = &smem[sl * SLICE_STRIDE_F + q];
        #pragma unroll
        for (int b = 0; b < 31; ++b)
            o[b * 4] = rb[b];
    }
    __syncthreads();

    // ---- Phase 4: coalesced streaming flush ----
    float* ob = out + (long)blockIdx.x * BLOCK_OUT_FLOATS;
    #pragma unroll
    for (int i = 0; i < BLOCK_OUT_FLOATS / THREADS; ++i) {   // 31 iters
        const int g   = i * THREADS + tid;
        const int slc = g / 124;            // const-div -> mul+shift
        const int r   = g - slc * 124;
        __stcs(&ob[g], smem[slc * SLICE_STRIDE_F + r]);
    }
}

}  // namespace

extern "C" void kernel_launch(void* const* d_in, const int* in_sizes, int n_in,
                              void* d_out, int out_size) {
    const float* x = (const float*)d_in[0];
    float* out = (float*)d_out;

    const long total_floats = (long)in_sizes[0];          // 67,108,864
    const long slices = total_floats / SLICE_FLOATS;      // 262,144
    const int blocks = (int)(slices / SLICES_PER_BLOCK);  // 8192

    hwtp_kernel<<<blocks, THREADS>>>(reinterpret_cast<const float4*>(x), out);
}